// round 13
// baseline (speedup 1.0000x reference)
#include <cuda_runtime.h>
#include <math.h>

#define HID  4096
#define NH   32
#define DD   128
#define II   4096
#define EPSF 1e-6f

#define RPH   514                 // rows per head in A: 384 qkv + 128 z + a + b
#define NB_C  148
#define NB_B  32
#define NB_A  2056                // 16448 / 8
#define A_BASE (NB_C + NB_B)      // 180
#define NW_C  (NB_C * 8)          // 1184 C warps

// ---------------- scratch (no device allocations allowed) ----------------
__device__ float g_qkv[3 * II];
__device__ float g_z[II];                 // raw z
__device__ float g_a[NH];
__device__ float g_b[NH];
__device__ float g_x[II];                 // cn * silu(z) (C's input vector)
__device__ unsigned g_acnt[NH];           // A rows done per head (monotonic)
__device__ unsigned g_bdone[NH];          // B heads done (monotonic)
__device__ unsigned g_bep[NH];            // per-B-block execution epoch
__device__ unsigned g_cep[NB_C];          // per-C-block execution epoch

__device__ __forceinline__ float siluf(float y) { return y / (1.f + expf(-y)); }

__global__ void __launch_bounds__(256, 5) fused_pipeline(
    const float* __restrict__ hs,
    const float* __restrict__ rnn_state,
    const float* __restrict__ conv_state,
    const float* __restrict__ Wqkv,
    const float* __restrict__ Wz,
    const float* __restrict__ Wa,
    const float* __restrict__ Wb,
    const float* __restrict__ conv_w,
    const float* __restrict__ conv_b,
    const float* __restrict__ A_log,
    const float* __restrict__ dt_bias,
    const float* __restrict__ norm_w,
    const float* __restrict__ Wout,
    float* __restrict__ out)
{
    __shared__ float4 sh4[HID / 4];       // 16KB; A: x-vector; B: scratch alias
    const int tid  = threadIdx.x;
    const int warp = tid >> 5;
    const int lane = tid & 31;
    const int bid  = blockIdx.x;

    float* out_state = out + II;
    float* out_conv  = out + II + (size_t)NH * DD * DD;

    if (bid >= A_BASE) {
        // ===================== A: fused GEMV, head-major rows =====================
        const float4* h4 = (const float4*)hs;
        #pragma unroll
        for (int i = tid; i < HID / 4; i += 256) sh4[i] = h4[i];
        __syncthreads();

        const int r   = (bid - A_BASE) * 8 + warp;   // 0..16447
        const int h   = r / RPH;
        const int sub = r - h * RPH;

        const float* Wrow;
        float* outp;
        if (sub < 384) {
            const int part = sub >> 7, e = sub & 127;
            Wrow = Wqkv + (size_t)(part * II + h * DD + e) * HID;
            outp = &g_qkv[part * II + h * DD + e];
        } else if (sub < 512) {
            const int e = sub - 384;
            Wrow = Wz + (size_t)(h * DD + e) * HID;
            outp = &g_z[h * DD + e];
        } else if (sub == 512) { Wrow = Wa + (size_t)h * HID; outp = &g_a[h]; }
        else                   { Wrow = Wb + (size_t)h * HID; outp = &g_b[h]; }

        const float4* W4 = (const float4*)Wrow;
        float a0 = 0.f, a1 = 0.f, a2 = 0.f, a3 = 0.f;
        #pragma unroll
        for (int j = lane; j < HID / 4; j += 128) {
            float4 w0 = W4[j      ], x0 = sh4[j      ];
            float4 w1 = W4[j +  32], x1 = sh4[j +  32];
            float4 w2 = W4[j +  64], x2 = sh4[j +  64];
            float4 w3 = W4[j +  96], x3 = sh4[j +  96];
            a0 += w0.x*x0.x + w0.y*x0.y + w0.z*x0.z + w0.w*x0.w;
            a1 += w1.x*x1.x + w1.y*x1.y + w1.z*x1.z + w1.w*x1.w;
            a2 += w2.x*x2.x + w2.y*x2.y + w2.z*x2.z + w2.w*x2.w;
            a3 += w3.x*x3.x + w3.y*x3.y + w3.z*x3.z + w3.w*x3.w;
        }
        float acc = (a0 + a1) + (a2 + a3);
        #pragma unroll
        for (int o = 16; o; o >>= 1) acc += __shfl_xor_sync(0xffffffffu, acc, o);
        if (lane == 0) {
            *outp = acc;
            __threadfence();                  // release: row visible before count
            atomicAdd(&g_acnt[h], 1u);
        }
    } else if (bid >= NB_C) {
        // ===================== B: delta-rule state update (1 block/head) ==========
        const int h = bid - NB_C;
        float* sm      = (float*)sh4;
        float* s_qkv   = sm;                  // 384
        float* s_kn    = sm + 384;            // 128
        float* s_qn    = sm + 512;            // 128
        float* s_delta = sm + 640;            // 128
        float* s_core  = sm + 768;            // 128
        float* s_part  = sm + 896;            // 256
        float* s_scal  = sm + 1152;           // 4
        __shared__ unsigned s_ep;

        if (tid == 0) s_ep = atomicAdd(&g_bep[h], 1u) + 1u;
        __syncthreads();
        const unsigned ep = s_ep;

        if (tid == 0) {
            while (*((volatile unsigned*)&g_acnt[h]) < ep * (unsigned)RPH)
                __nanosleep(200);
        }
        __syncthreads();
        __threadfence();                      // acquire

        // conv + silu for this head's 384 channels; write new conv state
        for (int c = tid; c < 384; c += 256) {
            const int part = c >> 7, e = c & 127;
            const int ch = part * II + h * DD + e;
            const float c0 = conv_state[ch*3+0], c1 = conv_state[ch*3+1], c2 = conv_state[ch*3+2];
            const float xn = g_qkv[ch];
            const float y = c0*conv_w[ch*4+0] + c1*conv_w[ch*4+1] + c2*conv_w[ch*4+2]
                          + xn*conv_w[ch*4+3] + conv_b[ch];
            s_qkv[c] = siluf(y);
            out_conv[ch*3+0] = c1; out_conv[ch*3+1] = c2; out_conv[ch*3+2] = xn;
        }
        __syncthreads();

        if (tid < 64) {
            const float* base = (tid < 32) ? s_qkv : (s_qkv + DD);
            const int l = tid & 31;
            float v0 = base[l], v1 = base[l+32], v2 = base[l+64], v3 = base[l+96];
            float x = v0*v0 + v1*v1 + v2*v2 + v3*v3;
            #pragma unroll
            for (int o = 16; o; o >>= 1) x += __shfl_xor_sync(0xffffffffu, x, o);
            if (l == 0) s_scal[tid >> 5] = x;
        }
        __syncthreads();
        if (tid < 128) {
            s_qn[tid] = s_qkv[tid]      / fmaxf(sqrtf(s_scal[0]), EPSF) * 0.08838834764831845f;
            s_kn[tid] = s_qkv[DD + tid] / fmaxf(sqrtf(s_scal[1]), EPSF);
        }
        __syncthreads();

        const float beta = 1.f / (1.f + expf(-g_b[h]));
        const float xg   = g_a[h] + dt_bias[h];
        const float sp   = (xg > 20.f) ? xg : log1pf(expf(xg));
        const float eg   = expf(-expf(A_log[h]) * sp);

        const int g = tid >> 7, e = tid & 127, d0 = g * 64;
        const float* st  = rnn_state + (size_t)h * DD * DD;
        float*       ost = out_state + (size_t)h * DD * DD;

        float kvp = 0.f;
        #pragma unroll 8
        for (int i = 0; i < 64; i++) kvp += st[(d0 + i) * DD + e] * s_kn[d0 + i];
        s_part[g * DD + e] = kvp;
        __syncthreads();
        if (tid < 128)
            s_delta[tid] = (s_qkv[2*DD + tid] - (s_part[tid] + s_part[DD + tid]) * eg) * beta;
        __syncthreads();

        const float delta = s_delta[e];
        float corep = 0.f;
        #pragma unroll 8
        for (int i = 0; i < 64; i++) {
            const float ns = st[(d0 + i) * DD + e] * eg + s_kn[d0 + i] * delta;
            ost[(d0 + i) * DD + e] = ns;
            corep += ns * s_qn[d0 + i];
        }
        s_part[g * DD + e] = corep;
        __syncthreads();
        if (tid < 128) s_core[tid] = s_part[tid] + s_part[DD + tid];
        __syncthreads();
        if (tid < 32) {
            float c0 = s_core[tid], c1 = s_core[tid+32], c2 = s_core[tid+64], c3 = s_core[tid+96];
            float x = c0*c0 + c1*c1 + c2*c2 + c3*c3;
            #pragma unroll
            for (int o = 16; o; o >>= 1) x += __shfl_xor_sync(0xffffffffu, x, o);
            if (tid == 0) s_scal[2] = x;
        }
        __syncthreads();
        if (tid < 128) {
            const float var = s_scal[2] * (1.f / DD);
            const float cn  = norm_w[tid] * s_core[tid] * rsqrtf(var + EPSF);
            g_x[h * DD + tid] = cn * siluf(g_z[h * DD + tid]);
        }
        __syncthreads();
        if (tid == 0) {
            __threadfence();                  // release g_x before flag
            atomicAdd(&g_bdone[h], 1u);
        }
    } else {
        // ===================== C: out = W_out @ x, chunk-major, head-gated ========
        __shared__ unsigned s_ep;
        if (tid == 0) s_ep = atomicAdd(&g_cep[bid], 1u) + 1u;
        __syncthreads();
        const unsigned ep = s_ep;

        const int gw = bid * 8 + warp;        // 0..1183
        int rows[4]; int nr = 0;
        for (int r = gw; r < HID; r += NW_C) rows[nr++] = r;
        float acc[4] = {0.f, 0.f, 0.f, 0.f};

        const float4* X4 = (const float4*)g_x;

        for (int h = 0; h < NH; h++) {
            while (*((volatile unsigned*)&g_bdone[h]) < ep) __nanosleep(200);
            __threadfence();                  // acquire g_x[h]

            const float4 xv = X4[h * 32 + lane];
            #pragma unroll
            for (int i = 0; i < 4; i++) {
                if (i < nr) {
                    const float4 w = ((const float4*)(Wout + (size_t)rows[i] * II))[h * 32 + lane];
                    acc[i] += w.x*xv.x + w.y*xv.y + w.z*xv.z + w.w*xv.w;
                }
            }
        }

        #pragma unroll
        for (int i = 0; i < 4; i++) {
            if (i < nr) {
                float a = acc[i];
                #pragma unroll
                for (int o = 16; o; o >>= 1) a += __shfl_xor_sync(0xffffffffu, a, o);
                if (lane == 0) out[rows[i]] = a;
            }
        }
    }
}

extern "C" void kernel_launch(void* const* d_in, const int* in_sizes, int n_in,
                              void* d_out, int out_size)
{
    const float* hs   = (const float*)d_in[0];
    const float* rnn  = (const float*)d_in[1];
    const float* cs   = (const float*)d_in[2];
    const float* Wqkv = (const float*)d_in[3];
    const float* Wz   = (const float*)d_in[4];
    const float* Wa   = (const float*)d_in[5];
    const float* Wb   = (const float*)d_in[6];
    const float* cw   = (const float*)d_in[7];
    const float* cb   = (const float*)d_in[8];
    const float* Alog = (const float*)d_in[9];
    const float* dtb  = (const float*)d_in[10];
    const float* nw   = (const float*)d_in[11];
    const float* Wout = (const float*)d_in[12];

    fused_pipeline<<<A_BASE + NB_A, 256>>>(
        hs, rnn, cs, Wqkv, Wz, Wa, Wb, cw, cb, Alog, dtb, nw, Wout,
        (float*)d_out);
}